// round 3
// baseline (speedup 1.0000x reference)
#include <cuda_runtime.h>
#include <math.h>

// Problem: B=64, T=512, V=50000, E=300, H1=256, H2=512, D1=128, D2=64, C=1
// Inputs: tokens, emb, W1x, W1h, b1, W2x, W2h, b2, Wd1, bd1, Wd2, bd2, Wc, bc

typedef unsigned long long ull;

// ---------------- packed f32x2 helpers ----------------
__device__ __forceinline__ ull pack2(float lo, float hi) {
    ull r; asm("mov.b64 %0,{%1,%2};" : "=l"(r) : "f"(lo), "f"(hi)); return r;
}
__device__ __forceinline__ ull splat2(float v) { return pack2(v, v); }
__device__ __forceinline__ float2 unpack2(ull v) {
    float2 r; asm("mov.b64 {%0,%1},%2;" : "=f"(r.x), "=f"(r.y) : "l"(v)); return r;
}
__device__ __forceinline__ ull fma2(ull a, ull b, ull c) {
    ull d; asm("fma.rn.f32x2 %0,%1,%2,%3;" : "=l"(d) : "l"(a), "l"(b), "l"(c)); return d;
}
__device__ __forceinline__ void cluster_sync_() {
    asm volatile("barrier.cluster.arrive.aligned;" ::: "memory");
    asm volatile("barrier.cluster.wait.aligned;" ::: "memory");
}

// ---------------- static device scratch ----------------
__device__ float g_xw1[(size_t)64 * 512 * 256];   // xw1[b][t][j]
__device__ float g_h1[64 * 256];
__device__ float g_h2[64 * 512];

// =====================================================================
// Kernel 1: xw1[b,t,:] = emb[tokens[b,t]] @ W1x + b1
// =====================================================================
__global__ void __launch_bounds__(256, 2)
embproj_kernel(const int* __restrict__ tokens, const float* __restrict__ emb,
               const float* __restrict__ W1x, const float* __restrict__ b1)
{
    __shared__ int    t_sm[32];
    __shared__ float4 a_sm[300 * 9];

    const int tid  = threadIdx.x;
    const int base = blockIdx.x * 32;

    if (tid < 32) t_sm[tid] = tokens[base + tid];
    __syncthreads();

    {
        const int m4 = tid >> 6;
        const int e0 = tid & 63;
        for (int mm = m4; mm < 8; mm += 4) {
            const int i0 = mm * 4;
            const size_t r0 = (size_t)t_sm[i0 + 0] * 300;
            const size_t r1 = (size_t)t_sm[i0 + 1] * 300;
            const size_t r2 = (size_t)t_sm[i0 + 2] * 300;
            const size_t r3 = (size_t)t_sm[i0 + 3] * 300;
            for (int e = e0; e < 300; e += 64) {
                float4 v;
                v.x = __ldg(emb + r0 + e);
                v.y = __ldg(emb + r1 + e);
                v.z = __ldg(emb + r2 + e);
                v.w = __ldg(emb + r3 + e);
                a_sm[e * 9 + mm] = v;
            }
        }
    }
    __syncthreads();

    const int j = tid;
    ull acc[16];
#pragma unroll
    for (int m = 0; m < 16; ++m) acc[m] = 0ull;

    const float* wp = W1x + j;
#pragma unroll 2
    for (int e = 0; e < 300; ++e) {
        const ull ws = splat2(__ldg(wp + (size_t)e * 256));
        const ulonglong2* ap = (const ulonglong2*)(a_sm + e * 9);
#pragma unroll
        for (int m2 = 0; m2 < 8; ++m2) {
            ulonglong2 s = ap[m2];
            acc[2 * m2]     = fma2(ws, s.x, acc[2 * m2]);
            acc[2 * m2 + 1] = fma2(ws, s.y, acc[2 * m2 + 1]);
        }
    }

    const float bj = __ldg(b1 + j);
#pragma unroll
    for (int m = 0; m < 16; ++m) {
        float2 v = unpack2(acc[m]);
        const size_t row = (size_t)(base + 2 * m);
        g_xw1[row * 256 + j]       = v.x + bj;
        g_xw1[(row + 1) * 256 + j] = v.y + bj;
    }
}

// =====================================================================
// Kernel 2: fused 2-layer recurrence (v2).
// 16 clusters x 8 CTAs, 256 threads. Cluster owns 4 batches; CTA rank r
// owns layer-1 cols [32r,32r+32) and layer-2 cols [64r,64r+64).
// Storage: W2h slice -> SMEM (128KB); W2x slice (32 ull) and W1h slice
// (16 ull) -> registers. h staged pre-splatted in SMEM; exchange via L2
// (stcg/ldcg) with ONE cluster barrier per step.
// =====================================================================
#define RNN_SMEM_BYTES (131072 + 24576 + 8192 + 8192 + 256)

__global__ void __cluster_dims__(8, 1, 1) __launch_bounds__(256, 1)
rnn_kernel(const float* __restrict__ W1h, const float* __restrict__ W2x,
           const float* __restrict__ W2h, const float* __restrict__ b2)
{
    extern __shared__ float smem[];
    float*  w2h_s = smem;                        // [512][64]   128 KB
    float4* hdAB  = (float4*)(smem + 32768);     // [768] {a,a,b,b}
    float4* hdCD  = hdAB + 768;                  // [768] {c,c,d,d}
    float*  red2  = (float*)(hdCD + 768);        // [8][32][8]   8 KB
    float*  red1  = red2 + 2048;                 // [16][16][8]  8 KB
    float*  b2_s  = red1 + 2048;                 // [64]

    const int tid  = threadIdx.x;
    const int rank = blockIdx.x & 7;
    const int b0   = (blockIdx.x >> 3) * 4;
    const int c1   = rank * 32, c2 = rank * 64;
    const int jp  = tid & 31, kg  = tid >> 5;    // layer-2 map: 8 kg x 32 colpairs
    const int jq  = tid & 15, kg1 = tid >> 4;    // layer-1 map: 16 kg x 16 colpairs

    // ---- W2h slice -> SMEM ----
    for (int idx = tid; idx < 512 * 64; idx += 256) {
        const int k = idx >> 6, j = idx & 63;
        w2h_s[idx] = W2h[(size_t)k * 512 + c2 + j];
    }
    // ---- W2x slice -> registers (32 ull) ----
    ull w2x_r[32];
#pragma unroll
    for (int r = 0; r < 32; ++r)
        w2x_r[r] = *(const ull*)(W2x + (size_t)(kg * 32 + r) * 512 + c2 + 2 * jp);
    // ---- W1h slice -> registers (16 ull) ----
    ull w1_r[16];
#pragma unroll
    for (int r = 0; r < 16; ++r)
        w1_r[r] = *(const ull*)(W1h + (size_t)(kg1 * 16 + r) * 256 + c1 + 2 * jq);
    if (tid < 64) b2_s[tid] = b2[c2 + tid];

    // ---- init: h1(0)=relu(xw1[:,0,:]); h2(-1)=0 ----
    if (tid < 128) {
        const int b = tid >> 5, jj = tid & 31;
        float v = g_xw1[(size_t)((b0 + b) * 512) * 256 + c1 + jj];
        __stcg(&g_h1[(b0 + b) * 256 + c1 + jj], fmaxf(v, 0.f));
    }
    {
        const int b = tid >> 6, jj = tid & 63;
        __stcg(&g_h2[(b0 + b) * 512 + c2 + jj], 0.f);
    }
    cluster_sync_();

    auto stage = [&]() {
#pragma unroll
        for (int it = 0; it < 3; ++it) {
            const int idx = tid + it * 256;
            float a, bb, c, d;
            if (idx < 256) {
                a  = __ldcg(&g_h1[(b0 + 0) * 256 + idx]);
                bb = __ldcg(&g_h1[(b0 + 1) * 256 + idx]);
                c  = __ldcg(&g_h1[(b0 + 2) * 256 + idx]);
                d  = __ldcg(&g_h1[(b0 + 3) * 256 + idx]);
            } else {
                const int km = idx - 256;
                a  = __ldcg(&g_h2[(b0 + 0) * 512 + km]);
                bb = __ldcg(&g_h2[(b0 + 1) * 512 + km]);
                c  = __ldcg(&g_h2[(b0 + 2) * 512 + km]);
                d  = __ldcg(&g_h2[(b0 + 3) * 512 + km]);
            }
            hdAB[idx] = make_float4(a, a, bb, bb);
            hdCD[idx] = make_float4(c, c, d, d);
        }
    };
    stage();
    __syncthreads();

    const int jf = tid & 63, bf = tid >> 6;     // layer-2 finish map
    const int fb = tid >> 5, fj = tid & 31;     // layer-1 finish map (tid<128)

    for (int t = 0; t < 512; ++t) {
        // prefetch xw1(t+1) early (L2 latency overlapped with compute)
        float xnext = 0.f;
        if (t < 511 && tid < 128)
            xnext = __ldcg(&g_xw1[((size_t)((b0 + fb) * 512 + t + 1)) * 256 + c1 + fj]);

        // ---- layer-2, h1 part (register weights) ----
        ull a0 = 0, a1 = 0, a2 = 0, a3 = 0;
        {
            const ulonglong2* pA = (const ulonglong2*)(hdAB + kg * 32);
            const ulonglong2* pC = (const ulonglong2*)(hdCD + kg * 32);
#pragma unroll
            for (int r = 0; r < 32; ++r) {
                const ulonglong2 sA = pA[r], sC = pC[r];
                a0 = fma2(w2x_r[r], sA.x, a0);
                a1 = fma2(w2x_r[r], sA.y, a1);
                a2 = fma2(w2x_r[r], sC.x, a2);
                a3 = fma2(w2x_r[r], sC.y, a3);
            }
        }
        // ---- layer-2, h2 part (SMEM weights) ----
        {
            const ulonglong2* pA = (const ulonglong2*)(hdAB + 256 + kg * 64);
            const ulonglong2* pC = (const ulonglong2*)(hdCD + 256 + kg * 64);
            const float* wp = w2h_s + (kg * 64) * 64 + 2 * jp;
#pragma unroll
            for (int r = 0; r < 64; ++r) {
                const ull w = *(const ull*)(wp + r * 64);
                const ulonglong2 sA = pA[r], sC = pC[r];
                a0 = fma2(w, sA.x, a0);
                a1 = fma2(w, sA.y, a1);
                a2 = fma2(w, sC.x, a2);
                a3 = fma2(w, sC.y, a3);
            }
        }
        {
            const float2 v0 = unpack2(a0), v1 = unpack2(a1);
            const float2 v2 = unpack2(a2), v3 = unpack2(a3);
            float4* q = (float4*)(red2 + (kg * 32 + jp) * 8);
            q[0] = make_float4(v0.x, v0.y, v1.x, v1.y);
            q[1] = make_float4(v2.x, v2.y, v3.x, v3.y);
        }
        // ---- layer-1 (register weights) ----
        {
            ull q0 = 0, q1 = 0, q2 = 0, q3 = 0;
            const ulonglong2* pA = (const ulonglong2*)(hdAB + kg1 * 16);
            const ulonglong2* pC = (const ulonglong2*)(hdCD + kg1 * 16);
#pragma unroll
            for (int r = 0; r < 16; ++r) {
                const ulonglong2 sA = pA[r], sC = pC[r];
                q0 = fma2(w1_r[r], sA.x, q0);
                q1 = fma2(w1_r[r], sA.y, q1);
                q2 = fma2(w1_r[r], sC.x, q2);
                q3 = fma2(w1_r[r], sC.y, q3);
            }
            const float2 u0 = unpack2(q0), u1 = unpack2(q1);
            const float2 u2 = unpack2(q2), u3 = unpack2(q3);
            float4* q = (float4*)(red1 + (kg1 * 16 + jq) * 8);
            q[0] = make_float4(u0.x, u0.y, u1.x, u1.y);
            q[1] = make_float4(u2.x, u2.y, u3.x, u3.y);
        }
        __syncthreads();

        // ---- finish layer-2: reduce 8 partials, bias, relu, publish ----
        {
            float s = b2_s[jf];
            const float* rp = red2 + (jf >> 1) * 8 + bf * 2 + (jf & 1);
#pragma unroll
            for (int g = 0; g < 8; ++g) s += rp[g * 256];
            __stcg(&g_h2[(b0 + bf) * 512 + c2 + jf], fmaxf(s, 0.f));
        }
        // ---- finish layer-1: reduce 16 partials + xw1(t+1), relu, publish ----
        if (t < 511 && tid < 128) {
            float s = xnext;
            const float* rp = red1 + (fj >> 1) * 8 + fb * 2 + (fj & 1);
#pragma unroll
            for (int g = 0; g < 16; ++g) s += rp[g * 128];
            __stcg(&g_h1[(b0 + fb) * 256 + c1 + fj], fmaxf(s, 0.f));
        }

        cluster_sync_();
        if (t < 511) {
            stage();
            __syncthreads();
        }
    }
}

// =====================================================================
// Kernel 3: MLP head
// =====================================================================
__global__ void __launch_bounds__(128, 1)
head_kernel(const float* __restrict__ Wd1, const float* __restrict__ bd1,
            const float* __restrict__ Wd2, const float* __restrict__ bd2,
            const float* __restrict__ Wc,  const float* __restrict__ bc,
            float* __restrict__ out)
{
    __shared__ float h_s[512], d1_s[128], d2_s[64];
    const int b = blockIdx.x, tid = threadIdx.x;

    for (int k = tid; k < 512; k += 128) h_s[k] = g_h2[b * 512 + k];
    __syncthreads();

    {
        float acc = __ldg(bd1 + tid);
#pragma unroll 4
        for (int k = 0; k < 512; ++k)
            acc = fmaf(h_s[k], __ldg(Wd1 + (size_t)k * 128 + tid), acc);
        d1_s[tid] = fmaxf(acc, 0.f);
    }
    __syncthreads();

    if (tid < 64) {
        float acc = __ldg(bd2 + tid);
#pragma unroll 4
        for (int k = 0; k < 128; ++k)
            acc = fmaf(d1_s[k], __ldg(Wd2 + (size_t)k * 64 + tid), acc);
        d2_s[tid] = fmaxf(acc, 0.f);
    }
    __syncthreads();

    if (tid < 32) {
        float p = d2_s[tid] * __ldg(Wc + tid) + d2_s[tid + 32] * __ldg(Wc + tid + 32);
#pragma unroll
        for (int o = 16; o; o >>= 1) p += __shfl_down_sync(0xffffffffu, p, o);
        if (tid == 0) out[b] = 1.f / (1.f + expf(-(p + __ldg(bc))));
    }
}

// =====================================================================
extern "C" void kernel_launch(void* const* d_in, const int* in_sizes, int n_in,
                              void* d_out, int out_size)
{
    const int*   tokens = (const int*)  d_in[0];
    const float* emb    = (const float*)d_in[1];
    const float* W1x    = (const float*)d_in[2];
    const float* W1h    = (const float*)d_in[3];
    const float* b1     = (const float*)d_in[4];
    const float* W2x    = (const float*)d_in[5];
    const float* W2h    = (const float*)d_in[6];
    const float* b2     = (const float*)d_in[7];
    const float* Wd1    = (const float*)d_in[8];
    const float* bd1    = (const float*)d_in[9];
    const float* Wd2    = (const float*)d_in[10];
    const float* bd2    = (const float*)d_in[11];
    const float* Wc     = (const float*)d_in[12];
    const float* bc     = (const float*)d_in[13];
    float* out = (float*)d_out;
    (void)in_sizes; (void)n_in; (void)out_size;

    static bool attr_done = false;
    if (!attr_done) {
        cudaFuncSetAttribute(rnn_kernel,
                             cudaFuncAttributeMaxDynamicSharedMemorySize,
                             RNN_SMEM_BYTES);
        attr_done = true;
    }

    embproj_kernel<<<1024, 256>>>(tokens, emb, W1x, b1);
    rnn_kernel<<<128, 256, RNN_SMEM_BYTES>>>(W1h, W2x, W2h, b2);
    head_kernel<<<64, 128>>>(Wd1, bd1, Wd2, bd2, Wc, bc, out);
}